// round 15
// baseline (speedup 1.0000x reference)
#include <cuda_runtime.h>

// ---------------------------------------------------------------------------
// BGATModel: B=262144 independent tiny graph-attention models.
// Rank-collapsed aggregation (R14) + k-loop unroll 4.
// ---------------------------------------------------------------------------

namespace {
constexpr int THREADS = 64;
constexpr float D_    = 50.0f;
constexpr float HZ_   = 5.0f;
constexpr float DMIN_ = 0.025f;
constexpr float PMAX_ = 1.0f;
constexpr float BMAX_ = 2.0f * 50.0f - 3.0f * 0.025f; // 99.925
constexpr float L2E_  = 1.4426950408889634f;
constexpr float AV6_  = 0.6f * 0.5f * L2E_;
constexpr float AV4_  = 0.4f * 0.5f * L2E_;

// shared float offsets
constexpr int CWU = 0;     // [d][k][c][h]   320
constexpr int CWA = 320;   //                320
constexpr int CWE = 640;   // [d][k][h]      160
constexpr int AV6 = 800;   // 160
constexpr int AV4 = 960;   // 160
constexpr int WRT = 1120;  // [d][c][i]      320 (Wres^T)
constexpr int GU0 = 1440;  // [d][k][j] sum_h W'u*Wa0   640
constexpr int GU1 = 2080;  // 640
constexpr int HU  = 2720;  // sum_h W'u*We              640
constexpr int RRU = 3360;  // [d][c][j] sum_i W'u*Wres  160
constexpr int GA0 = 3520;  // [d][k][j] sum_h W'a*Wu0   640
constexpr int GA1 = 4160;  // 640
constexpr int HAA = 4800;  // sum_h W'a*We              640
constexpr int SUN = 5440;  // [d][j] -sum_i w1g   80
constexpr int BUC = 5520;  // [d][j] b1+w1@lnb    80
constexpr int SAN = 5600;  constexpr int BAC = 5680;
constexpr int W2U = 5760;  // [d][j][2]          160
constexpr int W2A = 5920;
constexpr int B2U = 6080;  // 10 (pad 12)
constexpr int B2A = 6092;  // 10 (pad 12)
constexpr int RDW1 = 6104, RDB1 = 6136, RDW2 = 6144, RDB2 = 6176;
constexpr int RPW1 = 6180, RPB1 = 6212, RPW2 = 6220, RPB2 = 6252;
constexpr int WTOT = 6256;                     // divisible by 4
}

typedef unsigned long long ull;
struct Ptrs { const float* a[28]; };

__device__ __align__(16) float g_sW[WTOT];

__device__ __forceinline__ ull pk2(float lo, float hi) {
    ull r; asm("mov.b64 %0,{%1,%2};" : "=l"(r) : "f"(lo), "f"(hi)); return r;
}
__device__ __forceinline__ void upk2(ull v, float& lo, float& hi) {
    asm("mov.b64 {%0,%1},%2;" : "=f"(lo), "=f"(hi) : "l"(v));
}
__device__ __forceinline__ ull dupf(float x) { return pk2(x, x); }
__device__ __forceinline__ ull f2fma(ull a, ull b, ull c) {
    ull r; asm("fma.rn.f32x2 %0,%1,%2,%3;" : "=l"(r) : "l"(a), "l"(b), "l"(c)); return r;
}
__device__ __forceinline__ ull f2mul(ull a, ull b) {
    ull r; asm("mul.rn.f32x2 %0,%1,%2;" : "=l"(r) : "l"(a), "l"(b)); return r;
}
__device__ __forceinline__ ull f2add(ull a, ull b) {
    ull r; asm("add.rn.f32x2 %0,%1,%2;" : "=l"(r) : "l"(a), "l"(b)); return r;
}
__device__ __forceinline__ float ex2(float x) {
    float r; asm("ex2.approx.f32 %0,%1;" : "=f"(r) : "f"(x)); return r;
}

// ------------------- kernel 1: weight precompute (one block) ----------------
__global__ void bgat_prep(Ptrs p) {
    const int t = threadIdx.x;
    const int NT = blockDim.x;
    for (int x = t; x < 320; x += NT) {
        int d = x >> 6, k = (x >> 3) & 7, h = (x >> 1) & 3, c = x & 1;
        g_sW[CWU + (d * 8 + k) * 8 + c * 4 + h] = p.a[3][x];
        g_sW[CWA + (d * 8 + k) * 8 + c * 4 + h] = p.a[4][x];
    }
    for (int x = t; x < 160; x += NT) {
        g_sW[CWE + x] = p.a[5][x];
        g_sW[AV6 + x] = p.a[6][x] * AV6_;
        g_sW[AV4 + x] = p.a[6][x] * AV4_;
    }
    for (int x = t; x < 320; x += NT) {
        int d = x >> 6, i = (x >> 1) & 31, c = x & 1;
        g_sW[WRT + (d * 2 + c) * 32 + i] = p.a[7][x];
    }
    for (int x = t; x < 640; x += NT) {
        int dk = x >> 4, j = x & 15, d = dk >> 3;
        float g0 = 0.f, g1 = 0.f, hh = 0.f, a0 = 0.f, a1 = 0.f, ah = 0.f;
        for (int h = 0; h < 4; h++) {
            int i = (dk & 7) * 4 + h;
            float wu_ = p.a[12][d * 512 + j * 32 + i] * p.a[8][d * 32 + i];
            float wa_ = p.a[16][d * 512 + j * 32 + i] * p.a[10][d * 32 + i];
            float WA0 = p.a[4][(dk * 4 + h) * 2 + 0], WA1 = p.a[4][(dk * 4 + h) * 2 + 1];
            float WU0 = p.a[3][(dk * 4 + h) * 2 + 0], WU1 = p.a[3][(dk * 4 + h) * 2 + 1];
            float WE_ = p.a[5][dk * 4 + h];
            g0 += wu_ * WA0; g1 += wu_ * WA1; hh += wu_ * WE_;
            a0 += wa_ * WU0; a1 += wa_ * WU1; ah += wa_ * WE_;
        }
        g_sW[GU0 + x] = g0; g_sW[GU1 + x] = g1; g_sW[HU + x] = hh;
        g_sW[GA0 + x] = a0; g_sW[GA1 + x] = a1; g_sW[HAA + x] = ah;
    }
    for (int x = t; x < 160; x += NT) {
        int dc = x >> 4, j = x & 15, d = dc >> 1, c = dc & 1;
        float r = 0.f;
        for (int i = 0; i < 32; i++)
            r += p.a[12][d * 512 + j * 32 + i] * p.a[8][d * 32 + i] * p.a[7][d * 64 + i * 2 + c];
        g_sW[RRU + x] = r;
    }
    for (int x = t; x < 80; x += NT) {
        int d = x >> 4, j = x & 15;
        float su = 0.f, bu = 0.f, sa = 0.f, ba = 0.f;
        for (int i = 0; i < 32; i++) {
            float wu_ = p.a[12][(d * 16 + j) * 32 + i];
            float wa_ = p.a[16][(d * 16 + j) * 32 + i];
            su += wu_ * p.a[8][d * 32 + i];  bu += wu_ * p.a[9][d * 32 + i];
            sa += wa_ * p.a[10][d * 32 + i]; ba += wa_ * p.a[11][d * 32 + i];
        }
        g_sW[SUN + x] = -su; g_sW[BUC + x] = p.a[13][x] + bu;
        g_sW[SAN + x] = -sa; g_sW[BAC + x] = p.a[17][x] + ba;
    }
    for (int x = t; x < 160; x += NT) {
        int d = x >> 5, j = (x >> 1) & 15, c = x & 1;
        g_sW[W2U + d * 32 + j * 2 + c] = p.a[14][(d * 2 + c) * 16 + j];
        g_sW[W2A + d * 32 + j * 2 + c] = p.a[18][(d * 2 + c) * 16 + j];
    }
    for (int x = t; x < 12; x += NT) {
        g_sW[B2U + x] = (x < 10) ? p.a[15][x] : 0.f;
        g_sW[B2A + x] = (x < 10) ? p.a[19][x] : 0.f;
    }
    for (int x = t; x < 32; x += NT) {
        g_sW[RDW1 + x] = p.a[20][x]; g_sW[RDW2 + x] = p.a[22][x];
        g_sW[RPW1 + x] = p.a[24][x]; g_sW[RPW2 + x] = p.a[26][x];
    }
    for (int x = t; x < 8; x += NT) { g_sW[RDB1 + x] = p.a[21][x]; g_sW[RPB1 + x] = p.a[25][x]; }
    for (int x = t; x < 4; x += NT) { g_sW[RDB2 + x] = p.a[23][x]; g_sW[RPB2 + x] = p.a[27][x]; }
}

// ------------------------- kernel 2: the model ------------------------------
__global__ __launch_bounds__(THREADS, 6)
void bgat_kernel(const float* __restrict__ users,
                 const float* __restrict__ delta_init,
                 const float* __restrict__ power_init,
                 float* __restrict__ out, int B) {
    __shared__ __align__(16) float sW[WTOT];
    {
        const float4* src = (const float4*)g_sW;
        float4* dst = (float4*)sW;
        for (int i = threadIdx.x; i < WTOT / 4; i += THREADS) dst[i] = src[i];
    }
    __syncthreads();

    const int b = blockIdx.x * THREADS + threadIdx.x;
    if (b >= B) return;

    float uf[2][2], af[4][2];
    {
        float4 uv = ((const float4*)users)[b];
        uf[0][0] = uv.x; uf[0][1] = uv.y; uf[1][0] = uv.z; uf[1][1] = uv.w;
        float4 dv = ((const float4*)delta_init)[b];
        float4 pv = ((const float4*)power_init)[b];
        af[0][0] = pv.x; af[0][1] = dv.x; af[1][0] = pv.y; af[1][1] = dv.y;
        af[2][0] = pv.z; af[2][1] = dv.z; af[3][0] = pv.w; af[3][1] = dv.w;
    }

#pragma unroll 1
    for (int d = 0; d < 5; d++) {
        float da[4], xpos[4], sd = 1e-6f;
#pragma unroll
        for (int n = 0; n < 4; n++) { da[n] = fmaxf(af[n][1], 0.f); sd += da[n]; }
        float inv_sd = BMAX_ / fmaxf(sd, 1e-6f);
        { float cum = 0.f;
#pragma unroll
          for (int n = 0; n < 4; n++) { cum += da[n] * inv_sd; xpos[n] = cum - D_ + DMIN_ * (float)n; } }

        float es[2][4];
        ull dedg[2][4];
#pragma unroll
        for (int m = 0; m < 2; m++)
#pragma unroll
            for (int n = 0; n < 4; n++) {
                float dx = uf[m][0] - xpos[n], dy = uf[m][1];
                float e = sqrtf(fmaf(dx, dx, dy * dy));
                es[m][n] = e;
                dedg[m][n] = dupf(e);
            }

        ull duf0[2], duf1[2], daf0[4], daf1[4];
#pragma unroll
        for (int m = 0; m < 2; m++) { duf0[m] = dupf(uf[m][0]); duf1[m] = dupf(uf[m][1]); }
#pragma unroll
        for (int n = 0; n < 4; n++) { daf0[n] = dupf(af[n][0]); daf1[n] = dupf(af[n][1]); }

        ull uacc[2][8], aacc[4][8];
        ull usum[2], usq[2], asum[4], asq[4];
        {
            const ull* rr0 = (const ull*)&sW[RRU + (d * 2 + 0) * 16];
            const ull* rr1 = (const ull*)&sW[RRU + (d * 2 + 1) * 16];
#pragma unroll
            for (int m = 0; m < 2; m++) {
                usum[m] = 0ull; usq[m] = 0ull;
#pragma unroll
                for (int jp = 0; jp < 8; jp++)
                    uacc[m][jp] = f2fma(duf0[m], rr0[jp], f2mul(duf1[m], rr1[jp]));
            }
        }
#pragma unroll
        for (int n = 0; n < 4; n++) {
            asum[n] = 0ull; asq[n] = 0ull;
#pragma unroll
            for (int jp = 0; jp < 8; jp++) aacc[n][jp] = 0ull;
        }

#pragma unroll 4
        for (int k = 0; k < 8; k++) {
            const ull* wu2 = (const ull*)&sW[CWU + (d * 8 + k) * 8];
            const ull* wa2 = (const ull*)&sW[CWA + (d * 8 + k) * 8];
            const ull* we2 = (const ull*)&sW[CWE + (d * 8 + k) * 4];
            float4 a6 = *(const float4*)&sW[AV6 + (d * 8 + k) * 4];
            float4 a4 = *(const float4*)&sW[AV4 + (d * 8 + k) * 4];

            ull U2[2][2], A2[4][2];
#pragma unroll
            for (int m = 0; m < 2; m++) {
                U2[m][0] = f2fma(duf0[m], wu2[0], f2mul(duf1[m], wu2[2]));
                U2[m][1] = f2fma(duf0[m], wu2[1], f2mul(duf1[m], wu2[3]));
            }
#pragma unroll
            for (int n = 0; n < 4; n++) {
                A2[n][0] = f2fma(daf0[n], wa2[0], f2mul(daf1[n], wa2[2]));
                A2[n][1] = f2fma(daf0[n], wa2[1], f2mul(daf1[n], wa2[3]));
            }

            float alpha[2][4];
#pragma unroll
            for (int m = 0; m < 2; m++) {
                float sc[4];
#pragma unroll
                for (int n = 0; n < 4; n++) {
                    ull s0 = f2fma(dedg[m][n], we2[0], f2add(U2[m][0], A2[n][0]));
                    ull s1 = f2fma(dedg[m][n], we2[1], f2add(U2[m][1], A2[n][1]));
                    float t0, t1, t2, t3;
                    upk2(s0, t0, t1); upk2(s1, t2, t3);
                    float pa = fmaf(t0, a6.x, fmaf(t1, a6.y, fmaf(t2, a6.z, t3 * a6.w)));
                    float pb = fmaf(fabsf(t0), a4.x, fmaf(fabsf(t1), a4.y,
                               fmaf(fabsf(t2), a4.z, fabsf(t3) * a4.w)));
                    sc[n] = pa + pb;
                }
                float mx = fmaxf(fmaxf(sc[0], sc[1]), fmaxf(sc[2], sc[3]));
                float e0 = ex2(sc[0] - mx), e1 = ex2(sc[1] - mx);
                float e2 = ex2(sc[2] - mx), e3 = ex2(sc[3] - mx);
                float rs = __fdividef(1.0f, (e0 + e1) + (e2 + e3));
                alpha[m][0] = e0 * rs; alpha[m][1] = e1 * rs;
                alpha[m][2] = e2 * rs; alpha[m][3] = e3 * rs;
            }

            ull p0d[2], p1d[2], ped[2];
#pragma unroll
            for (int m = 0; m < 2; m++) {
                float P0 = fmaf(alpha[m][0], af[0][0], alpha[m][1] * af[1][0]) +
                           fmaf(alpha[m][2], af[2][0], alpha[m][3] * af[3][0]);
                float P1 = fmaf(alpha[m][0], af[0][1], alpha[m][1] * af[1][1]) +
                           fmaf(alpha[m][2], af[2][1], alpha[m][3] * af[3][1]);
                float PE = fmaf(alpha[m][0], es[m][0], alpha[m][1] * es[m][1]) +
                           fmaf(alpha[m][2], es[m][2], alpha[m][3] * es[m][3]);
                p0d[m] = dupf(P0); p1d[m] = dupf(P1); ped[m] = dupf(PE);
            }
            ull w0d[4], w1d[4], svd[4];
#pragma unroll
            for (int n = 0; n < 4; n++) {
                float W0 = fmaf(alpha[0][n], uf[0][0], alpha[1][n] * uf[1][0]);
                float W1 = fmaf(alpha[0][n], uf[0][1], alpha[1][n] * uf[1][1]);
                float SV = fmaf(alpha[0][n], es[0][n], alpha[1][n] * es[1][n]);
                w0d[n] = dupf(W0); w1d[n] = dupf(W1); svd[n] = dupf(SV);
            }

            {
                const ull* wr0 = (const ull*)&sW[WRT + (d * 2 + 0) * 32 + k * 4];
                const ull* wr1 = (const ull*)&sW[WRT + (d * 2 + 1) * 32 + k * 4];
#pragma unroll
                for (int m = 0; m < 2; m++) {
#pragma unroll
                    for (int hp = 0; hp < 2; hp++) {
                        ull resp = f2fma(duf0[m], wr0[hp], f2mul(duf1[m], wr1[hp]));
                        ull up = f2fma(p0d[m], wa2[hp],
                                 f2fma(p1d[m], wa2[2 + hp],
                                 f2fma(ped[m], we2[hp], resp)));
                        usum[m] = f2add(usum[m], up);
                        usq[m]  = f2fma(up, up, usq[m]);
                    }
                }
            }
#pragma unroll
            for (int n = 0; n < 4; n++) {
#pragma unroll
                for (int hp = 0; hp < 2; hp++) {
                    ull vp = f2fma(w0d[n], wu2[hp],
                             f2fma(w1d[n], wu2[2 + hp],
                             f2mul(svd[n], we2[hp])));
                    asum[n] = f2add(asum[n], vp);
                    asq[n]  = f2fma(vp, vp, asq[n]);
                }
            }

            {
                const ulonglong2* g0p = (const ulonglong2*)&sW[GU0 + (d * 8 + k) * 16];
                const ulonglong2* g1p = (const ulonglong2*)&sW[GU1 + (d * 8 + k) * 16];
                const ulonglong2* hup = (const ulonglong2*)&sW[HU  + (d * 8 + k) * 16];
#pragma unroll
                for (int q = 0; q < 4; q++) {
                    ulonglong2 g0 = g0p[q], g1 = g1p[q], hu = hup[q];
#pragma unroll
                    for (int m = 0; m < 2; m++) {
                        uacc[m][2*q]   = f2fma(p0d[m], g0.x, f2fma(p1d[m], g1.x,
                                         f2fma(ped[m], hu.x, uacc[m][2*q])));
                        uacc[m][2*q+1] = f2fma(p0d[m], g0.y, f2fma(p1d[m], g1.y,
                                         f2fma(ped[m], hu.y, uacc[m][2*q+1])));
                    }
                }
            }
            {
                const ulonglong2* g0p = (const ulonglong2*)&sW[GA0 + (d * 8 + k) * 16];
                const ulonglong2* g1p = (const ulonglong2*)&sW[GA1 + (d * 8 + k) * 16];
                const ulonglong2* hap = (const ulonglong2*)&sW[HAA + (d * 8 + k) * 16];
#pragma unroll
                for (int q = 0; q < 4; q++) {
                    ulonglong2 g0 = g0p[q], g1 = g1p[q], ha = hap[q];
#pragma unroll
                    for (int n = 0; n < 4; n++) {
                        aacc[n][2*q]   = f2fma(w0d[n], g0.x, f2fma(w1d[n], g1.x,
                                         f2fma(svd[n], ha.x, aacc[n][2*q])));
                        aacc[n][2*q+1] = f2fma(w0d[n], g0.y, f2fma(w1d[n], g1.y,
                                         f2fma(svd[n], ha.y, aacc[n][2*q+1])));
                    }
                }
            }
        }

        // -------- epilogue: finish LN + MLP per instance --------
        float ufn[2][2], afn[4][2];
        {
            const ull* sn = (const ull*)&sW[SUN + d * 16];
            const ull* bc = (const ull*)&sW[BUC + d * 16];
            const ull* w2 = (const ull*)&sW[W2U + d * 32];
            ull b2 = *(const ull*)&sW[B2U + d * 2];
#pragma unroll
            for (int m = 0; m < 2; m++) {
                float s0, s1, q0, q1;
                upk2(usum[m], s0, s1); upk2(usq[m], q0, q1);
                float mu = (s0 + s1) * (1.0f / 32.0f);
                float var = (q0 + q1) * (1.0f / 32.0f) - mu * mu;
                float rr = rsqrtf(var + 1e-5f);
                ull dmu = dupf(mu), drr = dupf(rr);
                ull o2a = b2, o2b = 0ull;
#pragma unroll
                for (int jp = 0; jp < 8; jp++) {
                    ull t2 = f2fma(dmu, sn[jp], uacc[m][jp]);
                    ull c2 = f2fma(drr, t2, bc[jp]);
                    float c0, c1; upk2(c2, c0, c1);
                    c0 = fmaxf(c0, 0.f); c1 = fmaxf(c1, 0.f);
                    o2a = f2fma(dupf(c0), w2[2 * jp], o2a);
                    o2b = f2fma(dupf(c1), w2[2 * jp + 1], o2b);
                }
                upk2(f2add(o2a, o2b), ufn[m][0], ufn[m][1]);
            }
        }
        {
            const ull* sn = (const ull*)&sW[SAN + d * 16];
            const ull* bc = (const ull*)&sW[BAC + d * 16];
            const ull* w2 = (const ull*)&sW[W2A + d * 32];
            ull b2 = *(const ull*)&sW[B2A + d * 2];
#pragma unroll
            for (int n = 0; n < 4; n++) {
                float s0, s1, q0, q1;
                upk2(asum[n], s0, s1); upk2(asq[n], q0, q1);
                float mu = (s0 + s1) * (1.0f / 32.0f);
                float var = (q0 + q1) * (1.0f / 32.0f) - mu * mu;
                float rr = rsqrtf(var + 1e-5f);
                ull dmu = dupf(mu), drr = dupf(rr);
                ull o2a = b2, o2b = 0ull;
#pragma unroll
                for (int jp = 0; jp < 8; jp++) {
                    ull t2 = f2fma(dmu, sn[jp], aacc[n][jp]);
                    ull c2 = f2fma(drr, t2, bc[jp]);
                    float c0, c1; upk2(c2, c0, c1);
                    c0 = fmaxf(c0, 0.f); c1 = fmaxf(c1, 0.f);
                    o2a = f2fma(dupf(c0), w2[2 * jp], o2a);
                    o2b = f2fma(dupf(c1), w2[2 * jp + 1], o2b);
                }
                upk2(f2add(o2a, o2b), afn[n][0], afn[n][1]);
            }
        }
#pragma unroll
        for (int m = 0; m < 2; m++) { uf[m][0] = ufn[m][0]; uf[m][1] = ufn[m][1]; }
#pragma unroll
        for (int n = 0; n < 4; n++) { af[n][0] = afn[n][0]; af[n][1] = afn[n][1]; }
    }

    // ---------------- readout heads ----------------
    float td[8];
#pragma unroll
    for (int i = 0; i < 8; i++) {
        float acc = sW[RDB1 + i];
#pragma unroll
        for (int n = 0; n < 4; n++) acc = fmaf(af[n][1], sW[RDW1 + i * 4 + n], acc);
        td[i] = fmaxf(acc, 0.f);
    }
    float daux[4], sumd = 0.f;
#pragma unroll
    for (int j = 0; j < 4; j++) {
        float acc = sW[RDB2 + j];
#pragma unroll
        for (int i = 0; i < 8; i++) acc = fmaf(td[i], sW[RDW2 + j * 8 + i], acc);
        daux[j] = fmaxf(acc, 0.001f);
        sumd += daux[j];
    }
    float fd = BMAX_ / sumd;
    float sdelta[4], x[4];
    { float cum = 0.f;
#pragma unroll
      for (int n = 0; n < 4; n++) {
          sdelta[n] = daux[n] * fd;
          cum += sdelta[n];
          x[n] = cum + DMIN_ * (float)n - D_ * (float)(n + 1);
      } }

    float tp[8];
#pragma unroll
    for (int i = 0; i < 8; i++) {
        float acc = sW[RPB1 + i];
#pragma unroll
        for (int n = 0; n < 4; n++) acc = fmaf(af[n][0], sW[RPW1 + i * 4 + n], acc);
        tp[i] = fmaxf(acc, 0.f);
    }
    float paux[4], sump = 1e-6f;
#pragma unroll
    for (int j = 0; j < 4; j++) {
        float acc = sW[RPB2 + j];
#pragma unroll
        for (int i = 0; i < 8; i++) acc = fmaf(tp[i], sW[RPW2 + j * 8 + i], acc);
        paux[j] = fmaxf(acc, 0.001f);
        sump += paux[j];
    }
    float fp = PMAX_ / fmaxf(PMAX_, sump);

    ((float4*)out)[b] = make_float4(paux[0] * fp, paux[1] * fp, paux[2] * fp, paux[3] * fp);
    ((float4*)(out + 4 * (size_t)B))[b] = make_float4(sdelta[0], sdelta[1], sdelta[2], sdelta[3]);
    float* op = out + 8 * (size_t)B + (size_t)b * 12;
    ((float4*)op)[0] = make_float4(x[0], 0.f, HZ_, x[1]);
    ((float4*)op)[1] = make_float4(0.f, HZ_, x[2], 0.f);
    ((float4*)op)[2] = make_float4(HZ_, x[3], 0.f, HZ_);
}

extern "C" void kernel_launch(void* const* d_in, const int* in_sizes, int n_in,
                              void* d_out, int out_size) {
    Ptrs p;
    for (int i = 0; i < 28; i++) p.a[i] = (const float*)d_in[i];
    int B = in_sizes[0] / 4;
    int grid = (B + THREADS - 1) / THREADS;
    bgat_prep<<<1, 128>>>(p);
    bgat_kernel<<<grid, THREADS>>>((const float*)d_in[0], (const float*)d_in[1],
                                   (const float*)d_in[2], (float*)d_out, B);
}

// round 16
// speedup vs baseline: 1.1929x; 1.1929x over previous
#include <cuda_runtime.h>

// ---------------------------------------------------------------------------
// BGATModel: B=262144 independent tiny graph-attention models.
// Rank-collapsed aggregation (R14, unroll 2) + born-duplicated coefficients:
// alpha dup'd once, coefficient sums computed in f32x2 on dup'd operands.
// ---------------------------------------------------------------------------

namespace {
constexpr int THREADS = 64;
constexpr float D_    = 50.0f;
constexpr float HZ_   = 5.0f;
constexpr float DMIN_ = 0.025f;
constexpr float PMAX_ = 1.0f;
constexpr float BMAX_ = 2.0f * 50.0f - 3.0f * 0.025f; // 99.925
constexpr float L2E_  = 1.4426950408889634f;
constexpr float AV6_  = 0.6f * 0.5f * L2E_;
constexpr float AV4_  = 0.4f * 0.5f * L2E_;

// shared float offsets
constexpr int CWU = 0;     // [d][k][c][h]   320
constexpr int CWA = 320;   //                320
constexpr int CWE = 640;   // [d][k][h]      160
constexpr int AV6 = 800;   // 160
constexpr int AV4 = 960;   // 160
constexpr int WRT = 1120;  // [d][c][i]      320 (Wres^T)
constexpr int GU0 = 1440;  // [d][k][j] sum_h W'u*Wa0   640
constexpr int GU1 = 2080;  // 640
constexpr int HU  = 2720;  // sum_h W'u*We              640
constexpr int RRU = 3360;  // [d][c][j] sum_i W'u*Wres  160
constexpr int GA0 = 3520;  // [d][k][j] sum_h W'a*Wu0   640
constexpr int GA1 = 4160;  // 640
constexpr int HAA = 4800;  // sum_h W'a*We              640
constexpr int SUN = 5440;  // [d][j] -sum_i w1g   80
constexpr int BUC = 5520;  // [d][j] b1+w1@lnb    80
constexpr int SAN = 5600;  constexpr int BAC = 5680;
constexpr int W2U = 5760;  // [d][j][2]          160
constexpr int W2A = 5920;
constexpr int B2U = 6080;  // 10 (pad 12)
constexpr int B2A = 6092;  // 10 (pad 12)
constexpr int RDW1 = 6104, RDB1 = 6136, RDW2 = 6144, RDB2 = 6176;
constexpr int RPW1 = 6180, RPB1 = 6212, RPW2 = 6220, RPB2 = 6252;
constexpr int WTOT = 6256;                     // divisible by 4
}

typedef unsigned long long ull;
struct Ptrs { const float* a[28]; };

__device__ __align__(16) float g_sW[WTOT];

__device__ __forceinline__ ull pk2(float lo, float hi) {
    ull r; asm("mov.b64 %0,{%1,%2};" : "=l"(r) : "f"(lo), "f"(hi)); return r;
}
__device__ __forceinline__ void upk2(ull v, float& lo, float& hi) {
    asm("mov.b64 {%0,%1},%2;" : "=f"(lo), "=f"(hi) : "l"(v));
}
__device__ __forceinline__ ull dupf(float x) { return pk2(x, x); }
__device__ __forceinline__ ull f2fma(ull a, ull b, ull c) {
    ull r; asm("fma.rn.f32x2 %0,%1,%2,%3;" : "=l"(r) : "l"(a), "l"(b), "l"(c)); return r;
}
__device__ __forceinline__ ull f2mul(ull a, ull b) {
    ull r; asm("mul.rn.f32x2 %0,%1,%2;" : "=l"(r) : "l"(a), "l"(b)); return r;
}
__device__ __forceinline__ ull f2add(ull a, ull b) {
    ull r; asm("add.rn.f32x2 %0,%1,%2;" : "=l"(r) : "l"(a), "l"(b)); return r;
}
__device__ __forceinline__ float ex2(float x) {
    float r; asm("ex2.approx.f32 %0,%1;" : "=f"(r) : "f"(x)); return r;
}

// ------------------- kernel 1: weight precompute (one block) ----------------
__global__ void bgat_prep(Ptrs p) {
    const int t = threadIdx.x;
    const int NT = blockDim.x;
    for (int x = t; x < 320; x += NT) {
        int d = x >> 6, k = (x >> 3) & 7, h = (x >> 1) & 3, c = x & 1;
        g_sW[CWU + (d * 8 + k) * 8 + c * 4 + h] = p.a[3][x];
        g_sW[CWA + (d * 8 + k) * 8 + c * 4 + h] = p.a[4][x];
    }
    for (int x = t; x < 160; x += NT) {
        g_sW[CWE + x] = p.a[5][x];
        g_sW[AV6 + x] = p.a[6][x] * AV6_;
        g_sW[AV4 + x] = p.a[6][x] * AV4_;
    }
    for (int x = t; x < 320; x += NT) {
        int d = x >> 6, i = (x >> 1) & 31, c = x & 1;
        g_sW[WRT + (d * 2 + c) * 32 + i] = p.a[7][x];
    }
    for (int x = t; x < 640; x += NT) {
        int dk = x >> 4, j = x & 15, d = dk >> 3;
        float g0 = 0.f, g1 = 0.f, hh = 0.f, a0 = 0.f, a1 = 0.f, ah = 0.f;
        for (int h = 0; h < 4; h++) {
            int i = (dk & 7) * 4 + h;
            float wu_ = p.a[12][d * 512 + j * 32 + i] * p.a[8][d * 32 + i];
            float wa_ = p.a[16][d * 512 + j * 32 + i] * p.a[10][d * 32 + i];
            float WA0 = p.a[4][(dk * 4 + h) * 2 + 0], WA1 = p.a[4][(dk * 4 + h) * 2 + 1];
            float WU0 = p.a[3][(dk * 4 + h) * 2 + 0], WU1 = p.a[3][(dk * 4 + h) * 2 + 1];
            float WE_ = p.a[5][dk * 4 + h];
            g0 += wu_ * WA0; g1 += wu_ * WA1; hh += wu_ * WE_;
            a0 += wa_ * WU0; a1 += wa_ * WU1; ah += wa_ * WE_;
        }
        g_sW[GU0 + x] = g0; g_sW[GU1 + x] = g1; g_sW[HU + x] = hh;
        g_sW[GA0 + x] = a0; g_sW[GA1 + x] = a1; g_sW[HAA + x] = ah;
    }
    for (int x = t; x < 160; x += NT) {
        int dc = x >> 4, j = x & 15, d = dc >> 1, c = dc & 1;
        float r = 0.f;
        for (int i = 0; i < 32; i++)
            r += p.a[12][d * 512 + j * 32 + i] * p.a[8][d * 32 + i] * p.a[7][d * 64 + i * 2 + c];
        g_sW[RRU + x] = r;
    }
    for (int x = t; x < 80; x += NT) {
        int d = x >> 4, j = x & 15;
        float su = 0.f, bu = 0.f, sa = 0.f, ba = 0.f;
        for (int i = 0; i < 32; i++) {
            float wu_ = p.a[12][(d * 16 + j) * 32 + i];
            float wa_ = p.a[16][(d * 16 + j) * 32 + i];
            su += wu_ * p.a[8][d * 32 + i];  bu += wu_ * p.a[9][d * 32 + i];
            sa += wa_ * p.a[10][d * 32 + i]; ba += wa_ * p.a[11][d * 32 + i];
        }
        g_sW[SUN + x] = -su; g_sW[BUC + x] = p.a[13][x] + bu;
        g_sW[SAN + x] = -sa; g_sW[BAC + x] = p.a[17][x] + ba;
    }
    for (int x = t; x < 160; x += NT) {
        int d = x >> 5, j = (x >> 1) & 15, c = x & 1;
        g_sW[W2U + d * 32 + j * 2 + c] = p.a[14][(d * 2 + c) * 16 + j];
        g_sW[W2A + d * 32 + j * 2 + c] = p.a[18][(d * 2 + c) * 16 + j];
    }
    for (int x = t; x < 12; x += NT) {
        g_sW[B2U + x] = (x < 10) ? p.a[15][x] : 0.f;
        g_sW[B2A + x] = (x < 10) ? p.a[19][x] : 0.f;
    }
    for (int x = t; x < 32; x += NT) {
        g_sW[RDW1 + x] = p.a[20][x]; g_sW[RDW2 + x] = p.a[22][x];
        g_sW[RPW1 + x] = p.a[24][x]; g_sW[RPW2 + x] = p.a[26][x];
    }
    for (int x = t; x < 8; x += NT) { g_sW[RDB1 + x] = p.a[21][x]; g_sW[RPB1 + x] = p.a[25][x]; }
    for (int x = t; x < 4; x += NT) { g_sW[RDB2 + x] = p.a[23][x]; g_sW[RPB2 + x] = p.a[27][x]; }
}

// ------------------------- kernel 2: the model ------------------------------
__global__ __launch_bounds__(THREADS, 6)
void bgat_kernel(const float* __restrict__ users,
                 const float* __restrict__ delta_init,
                 const float* __restrict__ power_init,
                 float* __restrict__ out, int B) {
    __shared__ __align__(16) float sW[WTOT];
    {
        const float4* src = (const float4*)g_sW;
        float4* dst = (float4*)sW;
        for (int i = threadIdx.x; i < WTOT / 4; i += THREADS) dst[i] = src[i];
    }
    __syncthreads();

    const int b = blockIdx.x * THREADS + threadIdx.x;
    if (b >= B) return;

    float uf[2][2], af[4][2];
    {
        float4 uv = ((const float4*)users)[b];
        uf[0][0] = uv.x; uf[0][1] = uv.y; uf[1][0] = uv.z; uf[1][1] = uv.w;
        float4 dv = ((const float4*)delta_init)[b];
        float4 pv = ((const float4*)power_init)[b];
        af[0][0] = pv.x; af[0][1] = dv.x; af[1][0] = pv.y; af[1][1] = dv.y;
        af[2][0] = pv.z; af[2][1] = dv.z; af[3][0] = pv.w; af[3][1] = dv.w;
    }

#pragma unroll 1
    for (int d = 0; d < 5; d++) {
        float da[4], xpos[4], sd = 1e-6f;
#pragma unroll
        for (int n = 0; n < 4; n++) { da[n] = fmaxf(af[n][1], 0.f); sd += da[n]; }
        float inv_sd = BMAX_ / fmaxf(sd, 1e-6f);
        { float cum = 0.f;
#pragma unroll
          for (int n = 0; n < 4; n++) { cum += da[n] * inv_sd; xpos[n] = cum - D_ + DMIN_ * (float)n; } }

        float es[2][4];
        ull dedg[2][4];
#pragma unroll
        for (int m = 0; m < 2; m++)
#pragma unroll
            for (int n = 0; n < 4; n++) {
                float dx = uf[m][0] - xpos[n], dy = uf[m][1];
                float e = sqrtf(fmaf(dx, dx, dy * dy));
                es[m][n] = e;
                dedg[m][n] = dupf(e);
            }

        ull duf0[2], duf1[2], daf0[4], daf1[4];
#pragma unroll
        for (int m = 0; m < 2; m++) { duf0[m] = dupf(uf[m][0]); duf1[m] = dupf(uf[m][1]); }
#pragma unroll
        for (int n = 0; n < 4; n++) { daf0[n] = dupf(af[n][0]); daf1[n] = dupf(af[n][1]); }

        ull uacc[2][8], aacc[4][8];
        ull usum[2], usq[2], asum[4], asq[4];
        {
            const ull* rr0 = (const ull*)&sW[RRU + (d * 2 + 0) * 16];
            const ull* rr1 = (const ull*)&sW[RRU + (d * 2 + 1) * 16];
#pragma unroll
            for (int m = 0; m < 2; m++) {
                usum[m] = 0ull; usq[m] = 0ull;
#pragma unroll
                for (int jp = 0; jp < 8; jp++)
                    uacc[m][jp] = f2fma(duf0[m], rr0[jp], f2mul(duf1[m], rr1[jp]));
            }
        }
#pragma unroll
        for (int n = 0; n < 4; n++) {
            asum[n] = 0ull; asq[n] = 0ull;
#pragma unroll
            for (int jp = 0; jp < 8; jp++) aacc[n][jp] = 0ull;
        }

#pragma unroll 2
        for (int k = 0; k < 8; k++) {
            const ull* wu2 = (const ull*)&sW[CWU + (d * 8 + k) * 8];
            const ull* wa2 = (const ull*)&sW[CWA + (d * 8 + k) * 8];
            const ull* we2 = (const ull*)&sW[CWE + (d * 8 + k) * 4];
            float4 a6 = *(const float4*)&sW[AV6 + (d * 8 + k) * 4];
            float4 a4 = *(const float4*)&sW[AV4 + (d * 8 + k) * 4];

            ull U2[2][2], A2[4][2];
#pragma unroll
            for (int m = 0; m < 2; m++) {
                U2[m][0] = f2fma(duf0[m], wu2[0], f2mul(duf1[m], wu2[2]));
                U2[m][1] = f2fma(duf0[m], wu2[1], f2mul(duf1[m], wu2[3]));
            }
#pragma unroll
            for (int n = 0; n < 4; n++) {
                A2[n][0] = f2fma(daf0[n], wa2[0], f2mul(daf1[n], wa2[2]));
                A2[n][1] = f2fma(daf0[n], wa2[1], f2mul(daf1[n], wa2[3]));
            }

            // scores (exp2 domain, leaky folded via |t|) + softmax -> dup'd alpha
            ull dal[2][4];
#pragma unroll
            for (int m = 0; m < 2; m++) {
                float sc[4];
#pragma unroll
                for (int n = 0; n < 4; n++) {
                    ull s0 = f2fma(dedg[m][n], we2[0], f2add(U2[m][0], A2[n][0]));
                    ull s1 = f2fma(dedg[m][n], we2[1], f2add(U2[m][1], A2[n][1]));
                    float t0, t1, t2, t3;
                    upk2(s0, t0, t1); upk2(s1, t2, t3);
                    float pa = fmaf(t0, a6.x, fmaf(t1, a6.y, fmaf(t2, a6.z, t3 * a6.w)));
                    float pb = fmaf(fabsf(t0), a4.x, fmaf(fabsf(t1), a4.y,
                               fmaf(fabsf(t2), a4.z, fabsf(t3) * a4.w)));
                    sc[n] = pa + pb;
                }
                float mx = fmaxf(fmaxf(sc[0], sc[1]), fmaxf(sc[2], sc[3]));
                float e0 = ex2(sc[0] - mx), e1 = ex2(sc[1] - mx);
                float e2 = ex2(sc[2] - mx), e3 = ex2(sc[3] - mx);
                float rs = __fdividef(1.0f, (e0 + e1) + (e2 + e3));
                dal[m][0] = dupf(e0 * rs); dal[m][1] = dupf(e1 * rs);
                dal[m][2] = dupf(e2 * rs); dal[m][3] = dupf(e3 * rs);
            }

            // ---- rank-3 coefficients, born-duplicated (all-dup operands) ----
            ull p0d[2], p1d[2], ped[2];
#pragma unroll
            for (int m = 0; m < 2; m++) {
                p0d[m] = f2fma(dal[m][0], daf0[0], f2fma(dal[m][1], daf0[1],
                         f2fma(dal[m][2], daf0[2], f2mul(dal[m][3], daf0[3]))));
                p1d[m] = f2fma(dal[m][0], daf1[0], f2fma(dal[m][1], daf1[1],
                         f2fma(dal[m][2], daf1[2], f2mul(dal[m][3], daf1[3]))));
                ped[m] = f2fma(dal[m][0], dedg[m][0], f2fma(dal[m][1], dedg[m][1],
                         f2fma(dal[m][2], dedg[m][2], f2mul(dal[m][3], dedg[m][3]))));
            }
            ull w0d[4], w1d[4], svd[4];
#pragma unroll
            for (int n = 0; n < 4; n++) {
                w0d[n] = f2fma(dal[0][n], duf0[0], f2mul(dal[1][n], duf0[1]));
                w1d[n] = f2fma(dal[0][n], duf1[0], f2mul(dal[1][n], duf1[1]));
                svd[n] = f2fma(dal[0][n], dedg[0][n], f2mul(dal[1][n], dedg[1][n]));
            }

            // ---- user stats (ucat values incl residual) ----
            {
                const ull* wr0 = (const ull*)&sW[WRT + (d * 2 + 0) * 32 + k * 4];
                const ull* wr1 = (const ull*)&sW[WRT + (d * 2 + 1) * 32 + k * 4];
#pragma unroll
                for (int m = 0; m < 2; m++) {
#pragma unroll
                    for (int hp = 0; hp < 2; hp++) {
                        ull resp = f2fma(duf0[m], wr0[hp], f2mul(duf1[m], wr1[hp]));
                        ull up = f2fma(p0d[m], wa2[hp],
                                 f2fma(p1d[m], wa2[2 + hp],
                                 f2fma(ped[m], we2[hp], resp)));
                        usum[m] = f2add(usum[m], up);
                        usq[m]  = f2fma(up, up, usq[m]);
                    }
                }
            }
            // ---- agent stats ----
#pragma unroll
            for (int n = 0; n < 4; n++) {
#pragma unroll
                for (int hp = 0; hp < 2; hp++) {
                    ull vp = f2fma(w0d[n], wu2[hp],
                             f2fma(w1d[n], wu2[2 + hp],
                             f2mul(svd[n], we2[hp])));
                    asum[n] = f2add(asum[n], vp);
                    asq[n]  = f2fma(vp, vp, asq[n]);
                }
            }

            // ---- uacc: W1-projected user features via G matrices ----
            {
                const ulonglong2* g0p = (const ulonglong2*)&sW[GU0 + (d * 8 + k) * 16];
                const ulonglong2* g1p = (const ulonglong2*)&sW[GU1 + (d * 8 + k) * 16];
                const ulonglong2* hup = (const ulonglong2*)&sW[HU  + (d * 8 + k) * 16];
#pragma unroll
                for (int q = 0; q < 4; q++) {
                    ulonglong2 g0 = g0p[q], g1 = g1p[q], hu = hup[q];
#pragma unroll
                    for (int m = 0; m < 2; m++) {
                        uacc[m][2*q]   = f2fma(p0d[m], g0.x, f2fma(p1d[m], g1.x,
                                         f2fma(ped[m], hu.x, uacc[m][2*q])));
                        uacc[m][2*q+1] = f2fma(p0d[m], g0.y, f2fma(p1d[m], g1.y,
                                         f2fma(ped[m], hu.y, uacc[m][2*q+1])));
                    }
                }
            }
            // ---- aacc: W1-projected agent features via G matrices ----
            {
                const ulonglong2* g0p = (const ulonglong2*)&sW[GA0 + (d * 8 + k) * 16];
                const ulonglong2* g1p = (const ulonglong2*)&sW[GA1 + (d * 8 + k) * 16];
                const ulonglong2* hap = (const ulonglong2*)&sW[HAA + (d * 8 + k) * 16];
#pragma unroll
                for (int q = 0; q < 4; q++) {
                    ulonglong2 g0 = g0p[q], g1 = g1p[q], ha = hap[q];
#pragma unroll
                    for (int n = 0; n < 4; n++) {
                        aacc[n][2*q]   = f2fma(w0d[n], g0.x, f2fma(w1d[n], g1.x,
                                         f2fma(svd[n], ha.x, aacc[n][2*q])));
                        aacc[n][2*q+1] = f2fma(w0d[n], g0.y, f2fma(w1d[n], g1.y,
                                         f2fma(svd[n], ha.y, aacc[n][2*q+1])));
                    }
                }
            }
        }

        // -------- epilogue: finish LN + MLP per instance --------
        float ufn[2][2], afn[4][2];
        {
            const ull* sn = (const ull*)&sW[SUN + d * 16];
            const ull* bc = (const ull*)&sW[BUC + d * 16];
            const ull* w2 = (const ull*)&sW[W2U + d * 32];
            ull b2 = *(const ull*)&sW[B2U + d * 2];
#pragma unroll
            for (int m = 0; m < 2; m++) {
                float s0, s1, q0, q1;
                upk2(usum[m], s0, s1); upk2(usq[m], q0, q1);
                float mu = (s0 + s1) * (1.0f / 32.0f);
                float var = (q0 + q1) * (1.0f / 32.0f) - mu * mu;
                float rr = rsqrtf(var + 1e-5f);
                ull dmu = dupf(mu), drr = dupf(rr);
                ull o2a = b2, o2b = 0ull;
#pragma unroll
                for (int jp = 0; jp < 8; jp++) {
                    ull t2 = f2fma(dmu, sn[jp], uacc[m][jp]);
                    ull c2 = f2fma(drr, t2, bc[jp]);
                    float c0, c1; upk2(c2, c0, c1);
                    c0 = fmaxf(c0, 0.f); c1 = fmaxf(c1, 0.f);
                    o2a = f2fma(dupf(c0), w2[2 * jp], o2a);
                    o2b = f2fma(dupf(c1), w2[2 * jp + 1], o2b);
                }
                upk2(f2add(o2a, o2b), ufn[m][0], ufn[m][1]);
            }
        }
        {
            const ull* sn = (const ull*)&sW[SAN + d * 16];
            const ull* bc = (const ull*)&sW[BAC + d * 16];
            const ull* w2 = (const ull*)&sW[W2A + d * 32];
            ull b2 = *(const ull*)&sW[B2A + d * 2];
#pragma unroll
            for (int n = 0; n < 4; n++) {
                float s0, s1, q0, q1;
                upk2(asum[n], s0, s1); upk2(asq[n], q0, q1);
                float mu = (s0 + s1) * (1.0f / 32.0f);
                float var = (q0 + q1) * (1.0f / 32.0f) - mu * mu;
                float rr = rsqrtf(var + 1e-5f);
                ull dmu = dupf(mu), drr = dupf(rr);
                ull o2a = b2, o2b = 0ull;
#pragma unroll
                for (int jp = 0; jp < 8; jp++) {
                    ull t2 = f2fma(dmu, sn[jp], aacc[n][jp]);
                    ull c2 = f2fma(drr, t2, bc[jp]);
                    float c0, c1; upk2(c2, c0, c1);
                    c0 = fmaxf(c0, 0.f); c1 = fmaxf(c1, 0.f);
                    o2a = f2fma(dupf(c0), w2[2 * jp], o2a);
                    o2b = f2fma(dupf(c1), w2[2 * jp + 1], o2b);
                }
                upk2(f2add(o2a, o2b), afn[n][0], afn[n][1]);
            }
        }
#pragma unroll
        for (int m = 0; m < 2; m++) { uf[m][0] = ufn[m][0]; uf[m][1] = ufn[m][1]; }
#pragma unroll
        for (int n = 0; n < 4; n++) { af[n][0] = afn[n][0]; af[n][1] = afn[n][1]; }
    }

    // ---------------- readout heads ----------------
    float td[8];
#pragma unroll
    for (int i = 0; i < 8; i++) {
        float acc = sW[RDB1 + i];
#pragma unroll
        for (int n = 0; n < 4; n++) acc = fmaf(af[n][1], sW[RDW1 + i * 4 + n], acc);
        td[i] = fmaxf(acc, 0.f);
    }
    float daux[4], sumd = 0.f;
#pragma unroll
    for (int j = 0; j < 4; j++) {
        float acc = sW[RDB2 + j];
#pragma unroll
        for (int i = 0; i < 8; i++) acc = fmaf(td[i], sW[RDW2 + j * 8 + i], acc);
        daux[j] = fmaxf(acc, 0.001f);
        sumd += daux[j];
    }
    float fd = BMAX_ / sumd;
    float sdelta[4], x[4];
    { float cum = 0.f;
#pragma unroll
      for (int n = 0; n < 4; n++) {
          sdelta[n] = daux[n] * fd;
          cum += sdelta[n];
          x[n] = cum + DMIN_ * (float)n - D_ * (float)(n + 1);
      } }

    float tp[8];
#pragma unroll
    for (int i = 0; i < 8; i++) {
        float acc = sW[RPB1 + i];
#pragma unroll
        for (int n = 0; n < 4; n++) acc = fmaf(af[n][0], sW[RPW1 + i * 4 + n], acc);
        tp[i] = fmaxf(acc, 0.f);
    }
    float paux[4], sump = 1e-6f;
#pragma unroll
    for (int j = 0; j < 4; j++) {
        float acc = sW[RPB2 + j];
#pragma unroll
        for (int i = 0; i < 8; i++) acc = fmaf(tp[i], sW[RPW2 + j * 8 + i], acc);
        paux[j] = fmaxf(acc, 0.001f);
        sump += paux[j];
    }
    float fp = PMAX_ / fmaxf(PMAX_, sump);

    ((float4*)out)[b] = make_float4(paux[0] * fp, paux[1] * fp, paux[2] * fp, paux[3] * fp);
    ((float4*)(out + 4 * (size_t)B))[b] = make_float4(sdelta[0], sdelta[1], sdelta[2], sdelta[3]);
    float* op = out + 8 * (size_t)B + (size_t)b * 12;
    ((float4*)op)[0] = make_float4(x[0], 0.f, HZ_, x[1]);
    ((float4*)op)[1] = make_float4(0.f, HZ_, x[2], 0.f);
    ((float4*)op)[2] = make_float4(HZ_, x[3], 0.f, HZ_);
}

extern "C" void kernel_launch(void* const* d_in, const int* in_sizes, int n_in,
                              void* d_out, int out_size) {
    Ptrs p;
    for (int i = 0; i < 28; i++) p.a[i] = (const float*)d_in[i];
    int B = in_sizes[0] / 4;
    int grid = (B + THREADS - 1) / THREADS;
    bgat_prep<<<1, 128>>>(p);
    bgat_kernel<<<grid, THREADS>>>((const float*)d_in[0], (const float*)d_in[1],
                                   (const float*)d_in[2], (float*)d_out, B);
}

// round 17
// speedup vs baseline: 1.2558x; 1.0528x over previous
#include <cuda_runtime.h>

// ---------------------------------------------------------------------------
// BGATModel: B=262144 independent tiny graph-attention models.
// R14 winner (rank-collapsed aggregation, unroll 2, scalar coefficients)
// with 128-thread blocks (same 12 warps/SM, halved staging, half the CTAs).
// ---------------------------------------------------------------------------

namespace {
constexpr int THREADS = 128;
constexpr float D_    = 50.0f;
constexpr float HZ_   = 5.0f;
constexpr float DMIN_ = 0.025f;
constexpr float PMAX_ = 1.0f;
constexpr float BMAX_ = 2.0f * 50.0f - 3.0f * 0.025f; // 99.925
constexpr float L2E_  = 1.4426950408889634f;
constexpr float AV6_  = 0.6f * 0.5f * L2E_;
constexpr float AV4_  = 0.4f * 0.5f * L2E_;

// shared float offsets
constexpr int CWU = 0;     // [d][k][c][h]   320
constexpr int CWA = 320;   //                320
constexpr int CWE = 640;   // [d][k][h]      160
constexpr int AV6 = 800;   // 160
constexpr int AV4 = 960;   // 160
constexpr int WRT = 1120;  // [d][c][i]      320 (Wres^T)
constexpr int GU0 = 1440;  // [d][k][j] sum_h W'u*Wa0   640
constexpr int GU1 = 2080;  // 640
constexpr int HU  = 2720;  // sum_h W'u*We              640
constexpr int RRU = 3360;  // [d][c][j] sum_i W'u*Wres  160
constexpr int GA0 = 3520;  // [d][k][j] sum_h W'a*Wu0   640
constexpr int GA1 = 4160;  // 640
constexpr int HAA = 4800;  // sum_h W'a*We              640
constexpr int SUN = 5440;  // [d][j] -sum_i w1g   80
constexpr int BUC = 5520;  // [d][j] b1+w1@lnb    80
constexpr int SAN = 5600;  constexpr int BAC = 5680;
constexpr int W2U = 5760;  // [d][j][2]          160
constexpr int W2A = 5920;
constexpr int B2U = 6080;  // 10 (pad 12)
constexpr int B2A = 6092;  // 10 (pad 12)
constexpr int RDW1 = 6104, RDB1 = 6136, RDW2 = 6144, RDB2 = 6176;
constexpr int RPW1 = 6180, RPB1 = 6212, RPW2 = 6220, RPB2 = 6252;
constexpr int WTOT = 6256;                     // divisible by 4
}

typedef unsigned long long ull;
struct Ptrs { const float* a[28]; };

__device__ __align__(16) float g_sW[WTOT];

__device__ __forceinline__ ull pk2(float lo, float hi) {
    ull r; asm("mov.b64 %0,{%1,%2};" : "=l"(r) : "f"(lo), "f"(hi)); return r;
}
__device__ __forceinline__ void upk2(ull v, float& lo, float& hi) {
    asm("mov.b64 {%0,%1},%2;" : "=f"(lo), "=f"(hi) : "l"(v));
}
__device__ __forceinline__ ull dupf(float x) { return pk2(x, x); }
__device__ __forceinline__ ull f2fma(ull a, ull b, ull c) {
    ull r; asm("fma.rn.f32x2 %0,%1,%2,%3;" : "=l"(r) : "l"(a), "l"(b), "l"(c)); return r;
}
__device__ __forceinline__ ull f2mul(ull a, ull b) {
    ull r; asm("mul.rn.f32x2 %0,%1,%2;" : "=l"(r) : "l"(a), "l"(b)); return r;
}
__device__ __forceinline__ ull f2add(ull a, ull b) {
    ull r; asm("add.rn.f32x2 %0,%1,%2;" : "=l"(r) : "l"(a), "l"(b)); return r;
}
__device__ __forceinline__ float ex2(float x) {
    float r; asm("ex2.approx.f32 %0,%1;" : "=f"(r) : "f"(x)); return r;
}

// ------------------- kernel 1: weight precompute (one block) ----------------
__global__ void bgat_prep(Ptrs p) {
    const int t = threadIdx.x;
    const int NT = blockDim.x;
    for (int x = t; x < 320; x += NT) {
        int d = x >> 6, k = (x >> 3) & 7, h = (x >> 1) & 3, c = x & 1;
        g_sW[CWU + (d * 8 + k) * 8 + c * 4 + h] = p.a[3][x];
        g_sW[CWA + (d * 8 + k) * 8 + c * 4 + h] = p.a[4][x];
    }
    for (int x = t; x < 160; x += NT) {
        g_sW[CWE + x] = p.a[5][x];
        g_sW[AV6 + x] = p.a[6][x] * AV6_;
        g_sW[AV4 + x] = p.a[6][x] * AV4_;
    }
    for (int x = t; x < 320; x += NT) {
        int d = x >> 6, i = (x >> 1) & 31, c = x & 1;
        g_sW[WRT + (d * 2 + c) * 32 + i] = p.a[7][x];
    }
    for (int x = t; x < 640; x += NT) {
        int dk = x >> 4, j = x & 15, d = dk >> 3;
        float g0 = 0.f, g1 = 0.f, hh = 0.f, a0 = 0.f, a1 = 0.f, ah = 0.f;
        for (int h = 0; h < 4; h++) {
            int i = (dk & 7) * 4 + h;
            float wu_ = p.a[12][d * 512 + j * 32 + i] * p.a[8][d * 32 + i];
            float wa_ = p.a[16][d * 512 + j * 32 + i] * p.a[10][d * 32 + i];
            float WA0 = p.a[4][(dk * 4 + h) * 2 + 0], WA1 = p.a[4][(dk * 4 + h) * 2 + 1];
            float WU0 = p.a[3][(dk * 4 + h) * 2 + 0], WU1 = p.a[3][(dk * 4 + h) * 2 + 1];
            float WE_ = p.a[5][dk * 4 + h];
            g0 += wu_ * WA0; g1 += wu_ * WA1; hh += wu_ * WE_;
            a0 += wa_ * WU0; a1 += wa_ * WU1; ah += wa_ * WE_;
        }
        g_sW[GU0 + x] = g0; g_sW[GU1 + x] = g1; g_sW[HU + x] = hh;
        g_sW[GA0 + x] = a0; g_sW[GA1 + x] = a1; g_sW[HAA + x] = ah;
    }
    for (int x = t; x < 160; x += NT) {
        int dc = x >> 4, j = x & 15, d = dc >> 1, c = dc & 1;
        float r = 0.f;
        for (int i = 0; i < 32; i++)
            r += p.a[12][d * 512 + j * 32 + i] * p.a[8][d * 32 + i] * p.a[7][d * 64 + i * 2 + c];
        g_sW[RRU + x] = r;
    }
    for (int x = t; x < 80; x += NT) {
        int d = x >> 4, j = x & 15;
        float su = 0.f, bu = 0.f, sa = 0.f, ba = 0.f;
        for (int i = 0; i < 32; i++) {
            float wu_ = p.a[12][(d * 16 + j) * 32 + i];
            float wa_ = p.a[16][(d * 16 + j) * 32 + i];
            su += wu_ * p.a[8][d * 32 + i];  bu += wu_ * p.a[9][d * 32 + i];
            sa += wa_ * p.a[10][d * 32 + i]; ba += wa_ * p.a[11][d * 32 + i];
        }
        g_sW[SUN + x] = -su; g_sW[BUC + x] = p.a[13][x] + bu;
        g_sW[SAN + x] = -sa; g_sW[BAC + x] = p.a[17][x] + ba;
    }
    for (int x = t; x < 160; x += NT) {
        int d = x >> 5, j = (x >> 1) & 15, c = x & 1;
        g_sW[W2U + d * 32 + j * 2 + c] = p.a[14][(d * 2 + c) * 16 + j];
        g_sW[W2A + d * 32 + j * 2 + c] = p.a[18][(d * 2 + c) * 16 + j];
    }
    for (int x = t; x < 12; x += NT) {
        g_sW[B2U + x] = (x < 10) ? p.a[15][x] : 0.f;
        g_sW[B2A + x] = (x < 10) ? p.a[19][x] : 0.f;
    }
    for (int x = t; x < 32; x += NT) {
        g_sW[RDW1 + x] = p.a[20][x]; g_sW[RDW2 + x] = p.a[22][x];
        g_sW[RPW1 + x] = p.a[24][x]; g_sW[RPW2 + x] = p.a[26][x];
    }
    for (int x = t; x < 8; x += NT) { g_sW[RDB1 + x] = p.a[21][x]; g_sW[RPB1 + x] = p.a[25][x]; }
    for (int x = t; x < 4; x += NT) { g_sW[RDB2 + x] = p.a[23][x]; g_sW[RPB2 + x] = p.a[27][x]; }
}

// ------------------------- kernel 2: the model ------------------------------
__global__ __launch_bounds__(THREADS, 3)
void bgat_kernel(const float* __restrict__ users,
                 const float* __restrict__ delta_init,
                 const float* __restrict__ power_init,
                 float* __restrict__ out, int B) {
    __shared__ __align__(16) float sW[WTOT];
    {
        const float4* src = (const float4*)g_sW;
        float4* dst = (float4*)sW;
        for (int i = threadIdx.x; i < WTOT / 4; i += THREADS) dst[i] = src[i];
    }
    __syncthreads();

    const int b = blockIdx.x * THREADS + threadIdx.x;
    if (b >= B) return;

    float uf[2][2], af[4][2];
    {
        float4 uv = ((const float4*)users)[b];
        uf[0][0] = uv.x; uf[0][1] = uv.y; uf[1][0] = uv.z; uf[1][1] = uv.w;
        float4 dv = ((const float4*)delta_init)[b];
        float4 pv = ((const float4*)power_init)[b];
        af[0][0] = pv.x; af[0][1] = dv.x; af[1][0] = pv.y; af[1][1] = dv.y;
        af[2][0] = pv.z; af[2][1] = dv.z; af[3][0] = pv.w; af[3][1] = dv.w;
    }

#pragma unroll 1
    for (int d = 0; d < 5; d++) {
        float da[4], xpos[4], sd = 1e-6f;
#pragma unroll
        for (int n = 0; n < 4; n++) { da[n] = fmaxf(af[n][1], 0.f); sd += da[n]; }
        float inv_sd = BMAX_ / fmaxf(sd, 1e-6f);
        { float cum = 0.f;
#pragma unroll
          for (int n = 0; n < 4; n++) { cum += da[n] * inv_sd; xpos[n] = cum - D_ + DMIN_ * (float)n; } }

        float es[2][4];
        ull dedg[2][4];
#pragma unroll
        for (int m = 0; m < 2; m++)
#pragma unroll
            for (int n = 0; n < 4; n++) {
                float dx = uf[m][0] - xpos[n], dy = uf[m][1];
                float e = sqrtf(fmaf(dx, dx, dy * dy));
                es[m][n] = e;
                dedg[m][n] = dupf(e);
            }

        ull duf0[2], duf1[2], daf0[4], daf1[4];
#pragma unroll
        for (int m = 0; m < 2; m++) { duf0[m] = dupf(uf[m][0]); duf1[m] = dupf(uf[m][1]); }
#pragma unroll
        for (int n = 0; n < 4; n++) { daf0[n] = dupf(af[n][0]); daf1[n] = dupf(af[n][1]); }

        ull uacc[2][8], aacc[4][8];
        ull usum[2], usq[2], asum[4], asq[4];
        {
            const ull* rr0 = (const ull*)&sW[RRU + (d * 2 + 0) * 16];
            const ull* rr1 = (const ull*)&sW[RRU + (d * 2 + 1) * 16];
#pragma unroll
            for (int m = 0; m < 2; m++) {
                usum[m] = 0ull; usq[m] = 0ull;
#pragma unroll
                for (int jp = 0; jp < 8; jp++)
                    uacc[m][jp] = f2fma(duf0[m], rr0[jp], f2mul(duf1[m], rr1[jp]));
            }
        }
#pragma unroll
        for (int n = 0; n < 4; n++) {
            asum[n] = 0ull; asq[n] = 0ull;
#pragma unroll
            for (int jp = 0; jp < 8; jp++) aacc[n][jp] = 0ull;
        }

#pragma unroll 2
        for (int k = 0; k < 8; k++) {
            const ull* wu2 = (const ull*)&sW[CWU + (d * 8 + k) * 8];
            const ull* wa2 = (const ull*)&sW[CWA + (d * 8 + k) * 8];
            const ull* we2 = (const ull*)&sW[CWE + (d * 8 + k) * 4];
            float4 a6 = *(const float4*)&sW[AV6 + (d * 8 + k) * 4];
            float4 a4 = *(const float4*)&sW[AV4 + (d * 8 + k) * 4];

            ull U2[2][2], A2[4][2];
#pragma unroll
            for (int m = 0; m < 2; m++) {
                U2[m][0] = f2fma(duf0[m], wu2[0], f2mul(duf1[m], wu2[2]));
                U2[m][1] = f2fma(duf0[m], wu2[1], f2mul(duf1[m], wu2[3]));
            }
#pragma unroll
            for (int n = 0; n < 4; n++) {
                A2[n][0] = f2fma(daf0[n], wa2[0], f2mul(daf1[n], wa2[2]));
                A2[n][1] = f2fma(daf0[n], wa2[1], f2mul(daf1[n], wa2[3]));
            }

            float alpha[2][4];
#pragma unroll
            for (int m = 0; m < 2; m++) {
                float sc[4];
#pragma unroll
                for (int n = 0; n < 4; n++) {
                    ull s0 = f2fma(dedg[m][n], we2[0], f2add(U2[m][0], A2[n][0]));
                    ull s1 = f2fma(dedg[m][n], we2[1], f2add(U2[m][1], A2[n][1]));
                    float t0, t1, t2, t3;
                    upk2(s0, t0, t1); upk2(s1, t2, t3);
                    float pa = fmaf(t0, a6.x, fmaf(t1, a6.y, fmaf(t2, a6.z, t3 * a6.w)));
                    float pb = fmaf(fabsf(t0), a4.x, fmaf(fabsf(t1), a4.y,
                               fmaf(fabsf(t2), a4.z, fabsf(t3) * a4.w)));
                    sc[n] = pa + pb;
                }
                float mx = fmaxf(fmaxf(sc[0], sc[1]), fmaxf(sc[2], sc[3]));
                float e0 = ex2(sc[0] - mx), e1 = ex2(sc[1] - mx);
                float e2 = ex2(sc[2] - mx), e3 = ex2(sc[3] - mx);
                float rs = __fdividef(1.0f, (e0 + e1) + (e2 + e3));
                alpha[m][0] = e0 * rs; alpha[m][1] = e1 * rs;
                alpha[m][2] = e2 * rs; alpha[m][3] = e3 * rs;
            }

            ull p0d[2], p1d[2], ped[2];
#pragma unroll
            for (int m = 0; m < 2; m++) {
                float P0 = fmaf(alpha[m][0], af[0][0], alpha[m][1] * af[1][0]) +
                           fmaf(alpha[m][2], af[2][0], alpha[m][3] * af[3][0]);
                float P1 = fmaf(alpha[m][0], af[0][1], alpha[m][1] * af[1][1]) +
                           fmaf(alpha[m][2], af[2][1], alpha[m][3] * af[3][1]);
                float PE = fmaf(alpha[m][0], es[m][0], alpha[m][1] * es[m][1]) +
                           fmaf(alpha[m][2], es[m][2], alpha[m][3] * es[m][3]);
                p0d[m] = dupf(P0); p1d[m] = dupf(P1); ped[m] = dupf(PE);
            }
            ull w0d[4], w1d[4], svd[4];
#pragma unroll
            for (int n = 0; n < 4; n++) {
                float W0 = fmaf(alpha[0][n], uf[0][0], alpha[1][n] * uf[1][0]);
                float W1 = fmaf(alpha[0][n], uf[0][1], alpha[1][n] * uf[1][1]);
                float SV = fmaf(alpha[0][n], es[0][n], alpha[1][n] * es[1][n]);
                w0d[n] = dupf(W0); w1d[n] = dupf(W1); svd[n] = dupf(SV);
            }

            {
                const ull* wr0 = (const ull*)&sW[WRT + (d * 2 + 0) * 32 + k * 4];
                const ull* wr1 = (const ull*)&sW[WRT + (d * 2 + 1) * 32 + k * 4];
#pragma unroll
                for (int m = 0; m < 2; m++) {
#pragma unroll
                    for (int hp = 0; hp < 2; hp++) {
                        ull resp = f2fma(duf0[m], wr0[hp], f2mul(duf1[m], wr1[hp]));
                        ull up = f2fma(p0d[m], wa2[hp],
                                 f2fma(p1d[m], wa2[2 + hp],
                                 f2fma(ped[m], we2[hp], resp)));
                        usum[m] = f2add(usum[m], up);
                        usq[m]  = f2fma(up, up, usq[m]);
                    }
                }
            }
#pragma unroll
            for (int n = 0; n < 4; n++) {
#pragma unroll
                for (int hp = 0; hp < 2; hp++) {
                    ull vp = f2fma(w0d[n], wu2[hp],
                             f2fma(w1d[n], wu2[2 + hp],
                             f2mul(svd[n], we2[hp])));
                    asum[n] = f2add(asum[n], vp);
                    asq[n]  = f2fma(vp, vp, asq[n]);
                }
            }

            {
                const ulonglong2* g0p = (const ulonglong2*)&sW[GU0 + (d * 8 + k) * 16];
                const ulonglong2* g1p = (const ulonglong2*)&sW[GU1 + (d * 8 + k) * 16];
                const ulonglong2* hup = (const ulonglong2*)&sW[HU  + (d * 8 + k) * 16];
#pragma unroll
                for (int q = 0; q < 4; q++) {
                    ulonglong2 g0 = g0p[q], g1 = g1p[q], hu = hup[q];
#pragma unroll
                    for (int m = 0; m < 2; m++) {
                        uacc[m][2*q]   = f2fma(p0d[m], g0.x, f2fma(p1d[m], g1.x,
                                         f2fma(ped[m], hu.x, uacc[m][2*q])));
                        uacc[m][2*q+1] = f2fma(p0d[m], g0.y, f2fma(p1d[m], g1.y,
                                         f2fma(ped[m], hu.y, uacc[m][2*q+1])));
                    }
                }
            }
            {
                const ulonglong2* g0p = (const ulonglong2*)&sW[GA0 + (d * 8 + k) * 16];
                const ulonglong2* g1p = (const ulonglong2*)&sW[GA1 + (d * 8 + k) * 16];
                const ulonglong2* hap = (const ulonglong2*)&sW[HAA + (d * 8 + k) * 16];
#pragma unroll
                for (int q = 0; q < 4; q++) {
                    ulonglong2 g0 = g0p[q], g1 = g1p[q], ha = hap[q];
#pragma unroll
                    for (int n = 0; n < 4; n++) {
                        aacc[n][2*q]   = f2fma(w0d[n], g0.x, f2fma(w1d[n], g1.x,
                                         f2fma(svd[n], ha.x, aacc[n][2*q])));
                        aacc[n][2*q+1] = f2fma(w0d[n], g0.y, f2fma(w1d[n], g1.y,
                                         f2fma(svd[n], ha.y, aacc[n][2*q+1])));
                    }
                }
            }
        }

        // -------- epilogue: finish LN + MLP per instance --------
        float ufn[2][2], afn[4][2];
        {
            const ull* sn = (const ull*)&sW[SUN + d * 16];
            const ull* bc = (const ull*)&sW[BUC + d * 16];
            const ull* w2 = (const ull*)&sW[W2U + d * 32];
            ull b2 = *(const ull*)&sW[B2U + d * 2];
#pragma unroll
            for (int m = 0; m < 2; m++) {
                float s0, s1, q0, q1;
                upk2(usum[m], s0, s1); upk2(usq[m], q0, q1);
                float mu = (s0 + s1) * (1.0f / 32.0f);
                float var = (q0 + q1) * (1.0f / 32.0f) - mu * mu;
                float rr = rsqrtf(var + 1e-5f);
                ull dmu = dupf(mu), drr = dupf(rr);
                ull o2a = b2, o2b = 0ull;
#pragma unroll
                for (int jp = 0; jp < 8; jp++) {
                    ull t2 = f2fma(dmu, sn[jp], uacc[m][jp]);
                    ull c2 = f2fma(drr, t2, bc[jp]);
                    float c0, c1; upk2(c2, c0, c1);
                    c0 = fmaxf(c0, 0.f); c1 = fmaxf(c1, 0.f);
                    o2a = f2fma(dupf(c0), w2[2 * jp], o2a);
                    o2b = f2fma(dupf(c1), w2[2 * jp + 1], o2b);
                }
                upk2(f2add(o2a, o2b), ufn[m][0], ufn[m][1]);
            }
        }
        {
            const ull* sn = (const ull*)&sW[SAN + d * 16];
            const ull* bc = (const ull*)&sW[BAC + d * 16];
            const ull* w2 = (const ull*)&sW[W2A + d * 32];
            ull b2 = *(const ull*)&sW[B2A + d * 2];
#pragma unroll
            for (int n = 0; n < 4; n++) {
                float s0, s1, q0, q1;
                upk2(asum[n], s0, s1); upk2(asq[n], q0, q1);
                float mu = (s0 + s1) * (1.0f / 32.0f);
                float var = (q0 + q1) * (1.0f / 32.0f) - mu * mu;
                float rr = rsqrtf(var + 1e-5f);
                ull dmu = dupf(mu), drr = dupf(rr);
                ull o2a = b2, o2b = 0ull;
#pragma unroll
                for (int jp = 0; jp < 8; jp++) {
                    ull t2 = f2fma(dmu, sn[jp], aacc[n][jp]);
                    ull c2 = f2fma(drr, t2, bc[jp]);
                    float c0, c1; upk2(c2, c0, c1);
                    c0 = fmaxf(c0, 0.f); c1 = fmaxf(c1, 0.f);
                    o2a = f2fma(dupf(c0), w2[2 * jp], o2a);
                    o2b = f2fma(dupf(c1), w2[2 * jp + 1], o2b);
                }
                upk2(f2add(o2a, o2b), afn[n][0], afn[n][1]);
            }
        }
#pragma unroll
        for (int m = 0; m < 2; m++) { uf[m][0] = ufn[m][0]; uf[m][1] = ufn[m][1]; }
#pragma unroll
        for (int n = 0; n < 4; n++) { af[n][0] = afn[n][0]; af[n][1] = afn[n][1]; }
    }

    // ---------------- readout heads ----------------
    float td[8];
#pragma unroll
    for (int i = 0; i < 8; i++) {
        float acc = sW[RDB1 + i];
#pragma unroll
        for (int n = 0; n < 4; n++) acc = fmaf(af[n][1], sW[RDW1 + i * 4 + n], acc);
        td[i] = fmaxf(acc, 0.f);
    }
    float daux[4], sumd = 0.f;
#pragma unroll
    for (int j = 0; j < 4; j++) {
        float acc = sW[RDB2 + j];
#pragma unroll
        for (int i = 0; i < 8; i++) acc = fmaf(td[i], sW[RDW2 + j * 8 + i], acc);
        daux[j] = fmaxf(acc, 0.001f);
        sumd += daux[j];
    }
    float fd = BMAX_ / sumd;
    float sdelta[4], x[4];
    { float cum = 0.f;
#pragma unroll
      for (int n = 0; n < 4; n++) {
          sdelta[n] = daux[n] * fd;
          cum += sdelta[n];
          x[n] = cum + DMIN_ * (float)n - D_ * (float)(n + 1);
      } }

    float tp[8];
#pragma unroll
    for (int i = 0; i < 8; i++) {
        float acc = sW[RPB1 + i];
#pragma unroll
        for (int n = 0; n < 4; n++) acc = fmaf(af[n][0], sW[RPW1 + i * 4 + n], acc);
        tp[i] = fmaxf(acc, 0.f);
    }
    float paux[4], sump = 1e-6f;
#pragma unroll
    for (int j = 0; j < 4; j++) {
        float acc = sW[RPB2 + j];
#pragma unroll
        for (int i = 0; i < 8; i++) acc = fmaf(tp[i], sW[RPW2 + j * 8 + i], acc);
        paux[j] = fmaxf(acc, 0.001f);
        sump += paux[j];
    }
    float fp = PMAX_ / fmaxf(PMAX_, sump);

    ((float4*)out)[b] = make_float4(paux[0] * fp, paux[1] * fp, paux[2] * fp, paux[3] * fp);
    ((float4*)(out + 4 * (size_t)B))[b] = make_float4(sdelta[0], sdelta[1], sdelta[2], sdelta[3]);
    float* op = out + 8 * (size_t)B + (size_t)b * 12;
    ((float4*)op)[0] = make_float4(x[0], 0.f, HZ_, x[1]);
    ((float4*)op)[1] = make_float4(0.f, HZ_, x[2], 0.f);
    ((float4*)op)[2] = make_float4(HZ_, x[3], 0.f, HZ_);
}

extern "C" void kernel_launch(void* const* d_in, const int* in_sizes, int n_in,
                              void* d_out, int out_size) {
    Ptrs p;
    for (int i = 0; i < 28; i++) p.a[i] = (const float*)d_in[i];
    int B = in_sizes[0] / 4;
    int grid = (B + THREADS - 1) / THREADS;
    bgat_prep<<<1, 128>>>(p);
    bgat_kernel<<<grid, THREADS>>>((const float*)d_in[0], (const float*)d_in[1],
                                   (const float*)d_in[2], (float*)d_out, B);
}